// round 3
// baseline (speedup 1.0000x reference)
#include <cuda_runtime.h>
#include <cuda_bf16.h>
#include <math.h>

#define N_NODES 50000
#define N_EDGES 600000
#define DF 128
#define KB3 768          // 3 * 256 split-bf16 K
#define NB_SCAN 49       // ceil(50000/1024)

typedef __nv_bfloat16 bf16;

// ---------------- scratch (device globals) ----------------
__device__ float g_h0[(size_t)N_NODES * DF];
__device__ float g_h1[(size_t)N_NODES * DF];
__device__ bf16  g_h0Hi[(size_t)N_NODES * DF];
__device__ bf16  g_h0Lo[(size_t)N_NODES * DF];
__device__ bf16  g_h1Hi[(size_t)N_NODES * DF];
__device__ bf16  g_h1Lo[(size_t)N_NODES * DF];
__device__ bf16  g_xHi[(size_t)N_NODES * DF];
__device__ bf16  g_xLo[(size_t)N_NODES * DF];
__device__ int   g_counts[N_NODES + 1];
__device__ int   g_offsets[N_NODES + 1];
__device__ int   g_cursor[N_NODES];
__device__ int   g_src_sorted[N_EDGES];
__device__ int   g_bsum[NB_SCAN];
__device__ bf16  g_BT1[128 * KB3];   // [n][k'] n-major
__device__ bf16  g_BT2[128 * KB3];

// ---------------- preprocessing ----------------
__global__ void zero_counts_kernel() {
    int i = blockIdx.x * blockDim.x + threadIdx.x;
    if (i <= N_NODES) g_counts[i] = 0;
}

__global__ void hist_kernel(const int* __restrict__ dst) {
    int i = blockIdx.x * blockDim.x + threadIdx.x;
    if (i < N_EDGES) atomicAdd(&g_counts[dst[i]], 1);
}

// phase 1: block-local exclusive scan + block sums
__global__ void scan1_kernel() {
    __shared__ int wsum[32];
    const int tid = threadIdx.x, lane = tid & 31, wid = tid >> 5;
    int i = blockIdx.x * 1024 + tid;
    int v = (i < N_NODES) ? g_counts[i] : 0;
    int x = v;
    #pragma unroll
    for (int o = 1; o < 32; o <<= 1) {
        int y = __shfl_up_sync(0xffffffffu, x, o);
        if (lane >= o) x += y;
    }
    if (lane == 31) wsum[wid] = x;
    __syncthreads();
    if (wid == 0) {
        int w = wsum[lane];
        #pragma unroll
        for (int o = 1; o < 32; o <<= 1) {
            int y = __shfl_up_sync(0xffffffffu, w, o);
            if (lane >= o) w += y;
        }
        wsum[lane] = w;
    }
    __syncthreads();
    int incl = x + (wid > 0 ? wsum[wid - 1] : 0);
    if (i < N_NODES) g_offsets[i] = incl - v;
    if (tid == 1023) g_bsum[blockIdx.x] = incl;
}

// phase 2+3 merged: each block recomputes its prefix over the 49 block sums
__global__ void scan3_kernel() {
    __shared__ int s_pre;
    const int tid = threadIdx.x;
    const int b = blockIdx.x;
    if (tid < 32) {
        int v0 = (tid < NB_SCAN) ? g_bsum[tid] : 0;
        int v1 = (tid + 32 < NB_SCAN) ? g_bsum[tid + 32] : 0;
        int c  = (tid < b ? v0 : 0) + (tid + 32 < b ? v1 : 0);
        int pre = __reduce_add_sync(0xffffffffu, c);
        if (tid == 0) s_pre = pre;
    }
    __syncthreads();
    int i = b * 1024 + tid;
    if (i < N_NODES) {
        int o = g_offsets[i] + s_pre;
        g_offsets[i] = o;
        g_cursor[i]  = o;
    }
    if (b == 0 && tid == 0) g_offsets[N_NODES] = N_EDGES;  // total is constant
}

__global__ void scatter_kernel(const int* __restrict__ src, const int* __restrict__ dst) {
    int i = blockIdx.x * blockDim.x + threadIdx.x;
    if (i < N_EDGES) {
        int d = dst[i];
        int p = atomicAdd(&g_cursor[d], 1);
        g_src_sorted[p] = src[i];
    }
}

// build BT for both layers + split x into hi/lo (merged)
__global__ void prep_kernel(const float* __restrict__ W1, const float* __restrict__ R1,
                            const float* __restrict__ W2, const float* __restrict__ R2,
                            const float* __restrict__ x) {
    int i = blockIdx.x * blockDim.x + threadIdx.x;
    if (i < 128 * KB3) {
        int n = i / KB3, k = i % KB3;
        int seg = k >> 8, kb = k & 255;
        float w1, w2;
        if (kb < 128) { w1 = W1[kb * DF + n];          w2 = W2[kb * DF + n]; }
        else          { w1 = R1[(kb - 128) * DF + n];  w2 = R2[(kb - 128) * DF + n]; }
        bf16 h1 = __float2bfloat16_rn(w1);
        bf16 h2 = __float2bfloat16_rn(w2);
        g_BT1[i] = (seg == 2) ? __float2bfloat16_rn(w1 - __bfloat162float(h1)) : h1;
        g_BT2[i] = (seg == 2) ? __float2bfloat16_rn(w2 - __bfloat162float(h2)) : h2;
    }
    if (i < N_NODES * DF) {
        float v = x[i];
        bf16 h = __float2bfloat16_rn(v);
        g_xHi[i] = h;
        g_xLo[i] = __float2bfloat16_rn(v - __bfloat162float(h));
    }
}

// ---------------- fused agg + tensor-core GEMM ----------------
// Per block: (1) scatter-max aggregate its 128 rows from hPrev via CSR into
// smem (bf16 hi/lo, ldmatrix layout), (2) K=768 split-bf16 MMA:
//   seg0: aggHi|xHi @ Bhi   seg1: aggLo|xLo @ Bhi   seg2: aggHi|xHi @ Blo
#define BK 32
#define PADK 40
#define PADA 136

#define SMEM_AS    0                               // 2*128*PADK bf16
#define SMEM_BS    (2 * 128 * PADK)                // 2*128*PADK bf16
#define SMEM_AGGHI (4 * 128 * PADK)                // 128*PADA bf16
#define SMEM_AGGLO (4 * 128 * PADK + 128 * PADA)
#define SMEM_ELEMS (4 * 128 * PADK + 2 * 128 * PADA)
#define SMEM_BYTES (SMEM_ELEMS * 2)

__global__ __launch_bounds__(256, 2)
void fused_kernel(const float* __restrict__ hPrev,
                  const bf16* __restrict__ xHi, const bf16* __restrict__ xLo,
                  const bf16* __restrict__ BT,  const float* __restrict__ bias,
                  float* __restrict__ out, bf16* __restrict__ oHi, bf16* __restrict__ oLo) {
    extern __shared__ bf16 sm[];
    bf16* As    = sm + SMEM_AS;
    bf16* Bs    = sm + SMEM_BS;
    bf16* AggHi = sm + SMEM_AGGHI;
    bf16* AggLo = sm + SMEM_AGGLO;

    const int tid  = threadIdx.x;
    const int wid  = tid >> 5, lane = tid & 31;
    const int mb   = blockIdx.x * 128;

    // ---------- prologue: aggregate this block's 128 rows ----------
    #pragma unroll 1
    for (int r = 0; r < 16; r++) {
        const int local = wid * 16 + r;
        const int grow  = mb + local;
        int beg = 0, end = 0;
        if (grow < N_NODES) { beg = g_offsets[grow]; end = g_offsets[grow + 1]; }

        float4 acc;
        acc.x = acc.y = acc.z = acc.w = -INFINITY;
        for (int j = beg; j < end; j += 32) {
            int idx = 0;
            if (j + lane < end) idx = g_src_sorted[j + lane];
            int cnt = end - j;
            if (cnt > 32) cnt = 32;
            int i = 0;
            for (; i + 4 <= cnt; i += 4) {
                int s0 = __shfl_sync(0xffffffffu, idx, i + 0);
                int s1 = __shfl_sync(0xffffffffu, idx, i + 1);
                int s2 = __shfl_sync(0xffffffffu, idx, i + 2);
                int s3 = __shfl_sync(0xffffffffu, idx, i + 3);
                float4 v0 = ((const float4*)(hPrev + (size_t)s0 * DF))[lane];
                float4 v1 = ((const float4*)(hPrev + (size_t)s1 * DF))[lane];
                float4 v2 = ((const float4*)(hPrev + (size_t)s2 * DF))[lane];
                float4 v3 = ((const float4*)(hPrev + (size_t)s3 * DF))[lane];
                v0.x = fmaxf(v0.x, v1.x); v0.y = fmaxf(v0.y, v1.y);
                v0.z = fmaxf(v0.z, v1.z); v0.w = fmaxf(v0.w, v1.w);
                v2.x = fmaxf(v2.x, v3.x); v2.y = fmaxf(v2.y, v3.y);
                v2.z = fmaxf(v2.z, v3.z); v2.w = fmaxf(v2.w, v3.w);
                acc.x = fmaxf(acc.x, fmaxf(v0.x, v2.x));
                acc.y = fmaxf(acc.y, fmaxf(v0.y, v2.y));
                acc.z = fmaxf(acc.z, fmaxf(v0.z, v2.z));
                acc.w = fmaxf(acc.w, fmaxf(v0.w, v2.w));
            }
            for (; i < cnt; i++) {
                int s = __shfl_sync(0xffffffffu, idx, i);
                float4 v = ((const float4*)(hPrev + (size_t)s * DF))[lane];
                acc.x = fmaxf(acc.x, v.x); acc.y = fmaxf(acc.y, v.y);
                acc.z = fmaxf(acc.z, v.z); acc.w = fmaxf(acc.w, v.w);
            }
        }
        if (beg == end) { acc.x = acc.y = acc.z = acc.w = 0.0f; }

        float vs[4] = {acc.x, acc.y, acc.z, acc.w};
        ushort4 hi4, lo4;
        unsigned short* hp = (unsigned short*)&hi4;
        unsigned short* lp = (unsigned short*)&lo4;
        #pragma unroll
        for (int q = 0; q < 4; q++) {
            bf16 h16 = __float2bfloat16_rn(vs[q]);
            bf16 l16 = __float2bfloat16_rn(vs[q] - __bfloat162float(h16));
            hp[q] = *(unsigned short*)&h16;
            lp[q] = *(unsigned short*)&l16;
        }
        *(ushort4*)(AggHi + local * PADA + lane * 4) = hi4;
        *(ushort4*)(AggLo + local * PADA + lane * 4) = lo4;
    }
    __syncthreads();

    // ---------- main loop ----------
    auto issue = [&](int t, int buf) {
        int kt  = t * BK;
        int seg = kt >> 8;
        int kb  = kt & 255;
        bool isX = (kb >= 128);
        const bf16* srcA = isX ? ((seg == 1) ? xLo : xHi) : nullptr;
        int colb = kb - 128;
        #pragma unroll
        for (int it = 0; it < 2; it++) {
            int c = tid + it * 256;
            int row = c >> 2, part = c & 3;
            if (isX) {
                int grow = mb + row;
                int gr   = (grow < N_NODES) ? grow : 0;
                int sz   = (grow < N_NODES) ? 16 : 0;
                const bf16* src = srcA + (size_t)gr * DF + colb + part * 8;
                unsigned int da = (unsigned int)__cvta_generic_to_shared(
                    As + buf * 128 * PADK + row * PADK + part * 8);
                asm volatile("cp.async.cg.shared.global [%0], [%1], 16, %2;\n"
                             :: "r"(da), "l"(src), "r"(sz));
            }
            {
                const bf16* src = BT + (size_t)row * KB3 + kt + part * 8;
                unsigned int da = (unsigned int)__cvta_generic_to_shared(
                    Bs + buf * 128 * PADK + row * PADK + part * 8);
                asm volatile("cp.async.cg.shared.global [%0], [%1], 16;\n"
                             :: "r"(da), "l"(src));
            }
        }
        asm volatile("cp.async.commit_group;\n" ::: "memory");
    };

    const int mBase = (wid >> 2) * 64;   // 2 warps in m
    const int nBase = (wid & 3) * 32;    // 4 warps in n

    float acc[4][4][4];
    #pragma unroll
    for (int a = 0; a < 4; a++)
        #pragma unroll
        for (int b = 0; b < 4; b++)
            #pragma unroll
            for (int c = 0; c < 4; c++) acc[a][b][c] = 0.f;

    // shared-address bases
    unsigned int aOffX = (unsigned int)__cvta_generic_to_shared(
        As + (mBase + (lane & 15)) * PADK + 8 * (lane >> 4));
    int r16 = lane & 15;
    unsigned int bOff = (unsigned int)__cvta_generic_to_shared(
        Bs + (nBase + (r16 & 7)) * PADK + 8 * (r16 >> 3));
    unsigned int aggHiOff = (unsigned int)__cvta_generic_to_shared(
        AggHi + (mBase + (lane & 15)) * PADA + 8 * (lane >> 4));
    unsigned int aggLoOff = (unsigned int)__cvta_generic_to_shared(
        AggLo + (mBase + (lane & 15)) * PADA + 8 * (lane >> 4));
    const unsigned int bufStride = 128 * PADK * 2;  // bytes

    issue(0, 0);
    const int NT = KB3 / BK;  // 24
    for (int t = 0; t < NT; t++) {
        asm volatile("cp.async.wait_group 0;\n" ::: "memory");
        __syncthreads();
        if (t + 1 < NT) issue(t + 1, (t + 1) & 1);
        int buf = t & 1;
        int kt  = t * BK;
        int seg = kt >> 8;
        int kb  = kt & 255;
        bool isAgg = (kb < 128);
        unsigned int aB = isAgg ? (((seg == 1) ? aggLoOff : aggHiOff) + kb * 2)
                                : (aOffX + buf * bufStride);
        unsigned int aMT = isAgg ? (16 * PADA * 2) : (16 * PADK * 2);
        unsigned int bB = bOff + buf * bufStride;
        #pragma unroll
        for (int ks = 0; ks < 2; ks++) {
            unsigned int af[4][4], bfr[4][2];
            #pragma unroll
            for (int mt = 0; mt < 4; mt++) {
                unsigned int addr = aB + mt * aMT + ks * 32;
                asm volatile("ldmatrix.sync.aligned.m8n8.x4.shared.b16 {%0,%1,%2,%3}, [%4];\n"
                    : "=r"(af[mt][0]), "=r"(af[mt][1]), "=r"(af[mt][2]), "=r"(af[mt][3])
                    : "r"(addr));
            }
            #pragma unroll
            for (int nt = 0; nt < 4; nt++) {
                unsigned int addr = bB + nt * (8 * PADK * 2) + ks * 32;
                asm volatile("ldmatrix.sync.aligned.m8n8.x2.shared.b16 {%0,%1}, [%2];\n"
                    : "=r"(bfr[nt][0]), "=r"(bfr[nt][1]) : "r"(addr));
            }
            #pragma unroll
            for (int mt = 0; mt < 4; mt++)
                #pragma unroll
                for (int nt = 0; nt < 4; nt++)
                    asm volatile(
                        "mma.sync.aligned.m16n8k16.row.col.f32.bf16.bf16.f32 "
                        "{%0,%1,%2,%3}, {%4,%5,%6,%7}, {%8,%9}, {%0,%1,%2,%3};\n"
                        : "+f"(acc[mt][nt][0]), "+f"(acc[mt][nt][1]),
                          "+f"(acc[mt][nt][2]), "+f"(acc[mt][nt][3])
                        : "r"(af[mt][0]), "r"(af[mt][1]), "r"(af[mt][2]), "r"(af[mt][3]),
                          "r"(bfr[nt][0]), "r"(bfr[nt][1]));
        }
    }

    // ---------- epilogue ----------
    float2 bv[4];
    #pragma unroll
    for (int nt = 0; nt < 4; nt++) {
        int col = nBase + nt * 8 + (lane & 3) * 2;
        bv[nt].x = bias[col];
        bv[nt].y = bias[col + 1];
    }
    #pragma unroll
    for (int mt = 0; mt < 4; mt++) {
        #pragma unroll
        for (int half = 0; half < 2; half++) {
            int row = mb + mBase + mt * 16 + (lane >> 2) + half * 8;
            if (row >= N_NODES) continue;
            #pragma unroll
            for (int nt = 0; nt < 4; nt++) {
                int col = nBase + nt * 8 + (lane & 3) * 2;
                float v0 = fmaxf(acc[mt][nt][half * 2 + 0] + bv[nt].x, 0.f);
                float v1 = fmaxf(acc[mt][nt][half * 2 + 1] + bv[nt].y, 0.f);
                *(float2*)(out + (size_t)row * DF + col) = make_float2(v0, v1);
                if (oHi != nullptr) {
                    bf16 h0 = __float2bfloat16_rn(v0);
                    bf16 h1 = __float2bfloat16_rn(v1);
                    __nv_bfloat162 hp; hp.x = h0; hp.y = h1;
                    *(__nv_bfloat162*)(oHi + (size_t)row * DF + col) = hp;
                    __nv_bfloat162 lp;
                    lp.x = __float2bfloat16_rn(v0 - __bfloat162float(h0));
                    lp.y = __float2bfloat16_rn(v1 - __bfloat162float(h1));
                    *(__nv_bfloat162*)(oLo + (size_t)row * DF + col) = lp;
                }
            }
        }
    }
}

// ---------------- launch ----------------
extern "C" void kernel_launch(void* const* d_in, const int* in_sizes, int n_in,
                              void* d_out, int out_size) {
    const float* x  = (const float*)d_in[0];
    const int*   ei = (const int*)d_in[1];
    const float* W1 = (const float*)d_in[2];
    const float* b1 = (const float*)d_in[3];
    const float* R1 = (const float*)d_in[4];
    const float* W2 = (const float*)d_in[5];
    const float* b2 = (const float*)d_in[6];
    const float* R2 = (const float*)d_in[7];
    float* out = (float*)d_out;

    const int* src = ei;
    const int* dst = ei + N_EDGES;

    float *p_h0, *p_h1;
    bf16 *p_h0Hi, *p_h0Lo, *p_h1Hi, *p_h1Lo, *p_xHi, *p_xLo, *p_BT1, *p_BT2;
    cudaGetSymbolAddress((void**)&p_h0,   g_h0);
    cudaGetSymbolAddress((void**)&p_h1,   g_h1);
    cudaGetSymbolAddress((void**)&p_h0Hi, g_h0Hi);
    cudaGetSymbolAddress((void**)&p_h0Lo, g_h0Lo);
    cudaGetSymbolAddress((void**)&p_h1Hi, g_h1Hi);
    cudaGetSymbolAddress((void**)&p_h1Lo, g_h1Lo);
    cudaGetSymbolAddress((void**)&p_xHi,  g_xHi);
    cudaGetSymbolAddress((void**)&p_xLo,  g_xLo);
    cudaGetSymbolAddress((void**)&p_BT1,  g_BT1);
    cudaGetSymbolAddress((void**)&p_BT2,  g_BT2);

    static bool attrSet = false;
    if (!attrSet) {
        cudaFuncSetAttribute(fused_kernel,
                             cudaFuncAttributeMaxDynamicSharedMemorySize, SMEM_BYTES);
        attrSet = true;
    }

    // preprocessing
    zero_counts_kernel<<<(N_NODES + 256) / 256, 256>>>();
    hist_kernel<<<(N_EDGES + 255) / 256, 256>>>(dst);
    scan1_kernel<<<NB_SCAN, 1024>>>();
    scan3_kernel<<<NB_SCAN, 1024>>>();
    scatter_kernel<<<(N_EDGES + 255) / 256, 256>>>(src, dst);
    prep_kernel<<<(N_NODES * DF + 255) / 256, 256>>>(W1, R1, W2, R2, x);

    const int gemmBlocks = (N_NODES + 127) / 128;

    // layer 1: agg(x) fused; A = [agg | x] -> h0
    fused_kernel<<<gemmBlocks, 256, SMEM_BYTES>>>(x, p_xHi, p_xLo, p_BT1, b1,
                                                  p_h0, p_h0Hi, p_h0Lo);
    // layer 2
    fused_kernel<<<gemmBlocks, 256, SMEM_BYTES>>>(p_h0, p_h0Hi, p_h0Lo, p_BT2, b2,
                                                  p_h1, p_h1Hi, p_h1Lo);
    // layer 3
    fused_kernel<<<gemmBlocks, 256, SMEM_BYTES>>>(p_h1, p_h1Hi, p_h1Lo, p_BT2, b2,
                                                  p_h0, p_h0Hi, p_h0Lo);
    // layer 4
    fused_kernel<<<gemmBlocks, 256, SMEM_BYTES>>>(p_h0, p_h0Hi, p_h0Lo, p_BT2, b2,
                                                  out, nullptr, nullptr);
}

// round 4
// speedup vs baseline: 1.3995x; 1.3995x over previous
#include <cuda_runtime.h>
#include <cuda_bf16.h>
#include <math.h>

#define N_NODES 50000
#define N_EDGES 600000
#define DF 128
#define KB3 768          // 3 * 256 split-bf16 K
#define NB_SCAN 49

typedef __nv_bfloat16 bf16;

// ---------------- scratch (device globals) ----------------
__device__ float g_h0[(size_t)N_NODES * DF];
__device__ float g_h1[(size_t)N_NODES * DF];
__device__ bf16  g_h0Hi[(size_t)N_NODES * DF];
__device__ bf16  g_h0Lo[(size_t)N_NODES * DF];
__device__ bf16  g_h1Hi[(size_t)N_NODES * DF];
__device__ bf16  g_h1Lo[(size_t)N_NODES * DF];
__device__ bf16  g_xHi[(size_t)N_NODES * DF];
__device__ bf16  g_xLo[(size_t)N_NODES * DF];
__device__ bf16  g_aggHi[(size_t)N_NODES * DF];
__device__ bf16  g_aggLo[(size_t)N_NODES * DF];
__device__ int   g_counts[N_NODES + 1];
__device__ int   g_offsets[N_NODES + 1];
__device__ int   g_cursor[N_NODES];
__device__ int   g_src_sorted[N_EDGES];
__device__ int   g_bsum[NB_SCAN];
__device__ bf16  g_BT1[128 * KB3];   // [n][k'] n-major
__device__ bf16  g_BT2[128 * KB3];

// ---------------- preprocessing ----------------
__global__ void zero_counts_kernel() {
    int i = blockIdx.x * blockDim.x + threadIdx.x;
    if (i <= N_NODES) g_counts[i] = 0;
}

__global__ void hist_kernel(const int* __restrict__ dst) {
    int i = blockIdx.x * blockDim.x + threadIdx.x;
    if (i < N_EDGES) atomicAdd(&g_counts[dst[i]], 1);
}

__global__ void scan1_kernel() {
    __shared__ int wsum[32];
    const int tid = threadIdx.x, lane = tid & 31, wid = tid >> 5;
    int i = blockIdx.x * 1024 + tid;
    int v = (i < N_NODES) ? g_counts[i] : 0;
    int x = v;
    #pragma unroll
    for (int o = 1; o < 32; o <<= 1) {
        int y = __shfl_up_sync(0xffffffffu, x, o);
        if (lane >= o) x += y;
    }
    if (lane == 31) wsum[wid] = x;
    __syncthreads();
    if (wid == 0) {
        int w = wsum[lane];
        #pragma unroll
        for (int o = 1; o < 32; o <<= 1) {
            int y = __shfl_up_sync(0xffffffffu, w, o);
            if (lane >= o) w += y;
        }
        wsum[lane] = w;
    }
    __syncthreads();
    int incl = x + (wid > 0 ? wsum[wid - 1] : 0);
    if (i < N_NODES) g_offsets[i] = incl - v;
    if (tid == 1023) g_bsum[blockIdx.x] = incl;
}

// phase 2+3 merged: each block recomputes its prefix over the 49 block sums
__global__ void scan3_kernel() {
    __shared__ int s_pre;
    const int tid = threadIdx.x;
    const int b = blockIdx.x;
    if (tid < 32) {
        int v0 = (tid < NB_SCAN) ? g_bsum[tid] : 0;
        int v1 = (tid + 32 < NB_SCAN) ? g_bsum[tid + 32] : 0;
        int c  = (tid < b ? v0 : 0) + (tid + 32 < b ? v1 : 0);
        int pre = __reduce_add_sync(0xffffffffu, c);
        if (tid == 0) s_pre = pre;
    }
    __syncthreads();
    int i = b * 1024 + tid;
    if (i < N_NODES) {
        int o = g_offsets[i] + s_pre;
        g_offsets[i] = o;
        g_cursor[i]  = o;
    }
    if (b == 0 && tid == 0) g_offsets[N_NODES] = N_EDGES;
}

__global__ void scatter_kernel(const int* __restrict__ src, const int* __restrict__ dst) {
    int i = blockIdx.x * blockDim.x + threadIdx.x;
    if (i < N_EDGES) {
        int d = dst[i];
        int p = atomicAdd(&g_cursor[d], 1);
        g_src_sorted[p] = src[i];
    }
}

// build BT for both layers + split x into hi/lo (merged)
__global__ void prep_kernel(const float* __restrict__ W1, const float* __restrict__ R1,
                            const float* __restrict__ W2, const float* __restrict__ R2,
                            const float* __restrict__ x) {
    int i = blockIdx.x * blockDim.x + threadIdx.x;
    if (i < 128 * KB3) {
        int n = i / KB3, k = i % KB3;
        int seg = k >> 8, kb = k & 255;
        float w1, w2;
        if (kb < 128) { w1 = W1[kb * DF + n];          w2 = W2[kb * DF + n]; }
        else          { w1 = R1[(kb - 128) * DF + n];  w2 = R2[(kb - 128) * DF + n]; }
        bf16 h1 = __float2bfloat16_rn(w1);
        bf16 h2 = __float2bfloat16_rn(w2);
        g_BT1[i] = (seg == 2) ? __float2bfloat16_rn(w1 - __bfloat162float(h1)) : h1;
        g_BT2[i] = (seg == 2) ? __float2bfloat16_rn(w2 - __bfloat162float(h2)) : h2;
    }
    if (i < N_NODES * DF) {
        float v = x[i];
        bf16 h = __float2bfloat16_rn(v);
        g_xHi[i] = h;
        g_xLo[i] = __float2bfloat16_rn(v - __bfloat162float(h));
    }
}

// ---------------- aggregation: one warp per node, CSR max-reduce ----------------
__global__ void agg_kernel(const float* __restrict__ h) {
    const int gw   = (blockIdx.x * blockDim.x + threadIdx.x) >> 5;
    const int lane = threadIdx.x & 31;
    if (gw >= N_NODES) return;
    const int beg = g_offsets[gw];
    const int end = g_offsets[gw + 1];

    float4 acc;
    acc.x = acc.y = acc.z = acc.w = -INFINITY;

    for (int j = beg; j < end; j += 32) {
        int idx = 0;
        if (j + lane < end) idx = g_src_sorted[j + lane];
        int cnt = end - j;
        if (cnt > 32) cnt = 32;
        int i = 0;
        for (; i + 4 <= cnt; i += 4) {
            int s0 = __shfl_sync(0xffffffffu, idx, i + 0);
            int s1 = __shfl_sync(0xffffffffu, idx, i + 1);
            int s2 = __shfl_sync(0xffffffffu, idx, i + 2);
            int s3 = __shfl_sync(0xffffffffu, idx, i + 3);
            float4 v0 = ((const float4*)(h + (size_t)s0 * DF))[lane];
            float4 v1 = ((const float4*)(h + (size_t)s1 * DF))[lane];
            float4 v2 = ((const float4*)(h + (size_t)s2 * DF))[lane];
            float4 v3 = ((const float4*)(h + (size_t)s3 * DF))[lane];
            v0.x = fmaxf(v0.x, v1.x); v0.y = fmaxf(v0.y, v1.y);
            v0.z = fmaxf(v0.z, v1.z); v0.w = fmaxf(v0.w, v1.w);
            v2.x = fmaxf(v2.x, v3.x); v2.y = fmaxf(v2.y, v3.y);
            v2.z = fmaxf(v2.z, v3.z); v2.w = fmaxf(v2.w, v3.w);
            acc.x = fmaxf(acc.x, fmaxf(v0.x, v2.x));
            acc.y = fmaxf(acc.y, fmaxf(v0.y, v2.y));
            acc.z = fmaxf(acc.z, fmaxf(v0.z, v2.z));
            acc.w = fmaxf(acc.w, fmaxf(v0.w, v2.w));
        }
        for (; i < cnt; i++) {
            int s = __shfl_sync(0xffffffffu, idx, i);
            float4 v = ((const float4*)(h + (size_t)s * DF))[lane];
            acc.x = fmaxf(acc.x, v.x); acc.y = fmaxf(acc.y, v.y);
            acc.z = fmaxf(acc.z, v.z); acc.w = fmaxf(acc.w, v.w);
        }
    }
    if (beg == end) { acc.x = acc.y = acc.z = acc.w = 0.0f; }

    float vs[4] = {acc.x, acc.y, acc.z, acc.w};
    ushort4 hi4, lo4;
    unsigned short* hp = (unsigned short*)&hi4;
    unsigned short* lp = (unsigned short*)&lo4;
    #pragma unroll
    for (int q = 0; q < 4; q++) {
        bf16 h16 = __float2bfloat16_rn(vs[q]);
        bf16 l16 = __float2bfloat16_rn(vs[q] - __bfloat162float(h16));
        hp[q] = *(unsigned short*)&h16;
        lp[q] = *(unsigned short*)&l16;
    }
    ((ushort4*)(g_aggHi + (size_t)gw * DF))[lane] = hi4;
    ((ushort4*)(g_aggLo + (size_t)gw * DF))[lane] = lo4;
}

// ---------------- tensor-core GEMM ----------------
// out[m][n] = relu( A'[m][0:768] @ BT[n][0:768] + bias[n] )
// A' k-blocks: [0,256)=hi[agg|x], [256,512)=lo[agg|x], [512,768)=hi[agg|x]
// BK=64, 3-stage cp.async pipeline, depth-2 prefetch.
#define BK 64
#define PADK 72
#define STAGE_E (128 * PADK)        // elems per array per stage
#define NSTAGE 3
#define SMEM_BYTES (NSTAGE * 2 * STAGE_E * 2)

__global__ __launch_bounds__(256, 2)
void gemm_kernel(const bf16* __restrict__ aggHi, const bf16* __restrict__ aggLo,
                 const bf16* __restrict__ xHi,  const bf16* __restrict__ xLo,
                 const bf16* __restrict__ BT,   const float* __restrict__ bias,
                 float* __restrict__ out, bf16* __restrict__ oHi, bf16* __restrict__ oLo) {
    extern __shared__ bf16 sm[];
    bf16* As = sm;                       // NSTAGE * STAGE_E
    bf16* Bs = sm + NSTAGE * STAGE_E;    // NSTAGE * STAGE_E

    const int tid = threadIdx.x;
    const int mb  = blockIdx.x * 128;

    auto issue = [&](int t, int buf) {
        int kt  = t * BK;
        int seg = kt >> 8;
        int kb  = kt & 255;
        const bf16* srcA;
        int colb;
        if (kb < 128) { srcA = (seg == 1) ? aggLo : aggHi; colb = kb; }
        else          { srcA = (seg == 1) ? xLo  : xHi;    colb = kb - 128; }
        #pragma unroll
        for (int it = 0; it < 4; it++) {
            int c = tid + it * 256;
            int row = c >> 3, part = c & 7;      // 8 chunks of 16B per 64-col row
            {   // A
                int grow = mb + row;
                int gr   = (grow < N_NODES) ? grow : 0;
                int sz   = (grow < N_NODES) ? 16 : 0;
                const bf16* src = srcA + (size_t)gr * DF + colb + part * 8;
                unsigned int da = (unsigned int)__cvta_generic_to_shared(
                    As + buf * STAGE_E + row * PADK + part * 8);
                asm volatile("cp.async.cg.shared.global [%0], [%1], 16, %2;\n"
                             :: "r"(da), "l"(src), "r"(sz));
            }
            {   // B
                const bf16* src = BT + (size_t)row * KB3 + kt + part * 8;
                unsigned int da = (unsigned int)__cvta_generic_to_shared(
                    Bs + buf * STAGE_E + row * PADK + part * 8);
                asm volatile("cp.async.cg.shared.global [%0], [%1], 16;\n"
                             :: "r"(da), "l"(src));
            }
        }
        asm volatile("cp.async.commit_group;\n" ::: "memory");
    };

    const int wid = tid >> 5, lane = tid & 31;
    const int mBase = (wid >> 2) * 64;   // 2 warps in m
    const int nBase = (wid & 3) * 32;    // 4 warps in n

    float acc[4][4][4];
    #pragma unroll
    for (int a = 0; a < 4; a++)
        #pragma unroll
        for (int b = 0; b < 4; b++)
            #pragma unroll
            for (int c = 0; c < 4; c++) acc[a][b][c] = 0.f;

    unsigned int aOff = (unsigned int)__cvta_generic_to_shared(
        As + (mBase + (lane & 15)) * PADK + 8 * (lane >> 4));
    int r16 = lane & 15;
    unsigned int bOff = (unsigned int)__cvta_generic_to_shared(
        Bs + (nBase + (r16 & 7)) * PADK + 8 * (r16 >> 3));
    const unsigned int stageB = STAGE_E * 2;  // bytes

    issue(0, 0);
    issue(1, 1);
    const int NT = KB3 / BK;  // 12
    for (int t = 0; t < NT; t++) {
        if (t == NT - 1) {
            asm volatile("cp.async.wait_group 0;\n" ::: "memory");
        } else {
            asm volatile("cp.async.wait_group 1;\n" ::: "memory");
        }
        __syncthreads();
        if (t + 2 < NT) issue(t + 2, (t + 2) % NSTAGE);
        int buf = t % NSTAGE;
        unsigned int aB = aOff + buf * stageB;
        unsigned int bB = bOff + buf * stageB;
        #pragma unroll
        for (int ks = 0; ks < 4; ks++) {
            unsigned int af[4][4], bfr[4][2];
            #pragma unroll
            for (int mt = 0; mt < 4; mt++) {
                unsigned int addr = aB + mt * (16 * PADK * 2) + ks * 32;
                asm volatile("ldmatrix.sync.aligned.m8n8.x4.shared.b16 {%0,%1,%2,%3}, [%4];\n"
                    : "=r"(af[mt][0]), "=r"(af[mt][1]), "=r"(af[mt][2]), "=r"(af[mt][3])
                    : "r"(addr));
            }
            #pragma unroll
            for (int nt = 0; nt < 4; nt++) {
                unsigned int addr = bB + nt * (8 * PADK * 2) + ks * 32;
                asm volatile("ldmatrix.sync.aligned.m8n8.x2.shared.b16 {%0,%1}, [%2];\n"
                    : "=r"(bfr[nt][0]), "=r"(bfr[nt][1]) : "r"(addr));
            }
            #pragma unroll
            for (int mt = 0; mt < 4; mt++)
                #pragma unroll
                for (int nt = 0; nt < 4; nt++)
                    asm volatile(
                        "mma.sync.aligned.m16n8k16.row.col.f32.bf16.bf16.f32 "
                        "{%0,%1,%2,%3}, {%4,%5,%6,%7}, {%8,%9}, {%0,%1,%2,%3};\n"
                        : "+f"(acc[mt][nt][0]), "+f"(acc[mt][nt][1]),
                          "+f"(acc[mt][nt][2]), "+f"(acc[mt][nt][3])
                        : "r"(af[mt][0]), "r"(af[mt][1]), "r"(af[mt][2]), "r"(af[mt][3]),
                          "r"(bfr[nt][0]), "r"(bfr[nt][1]));
        }
    }

    // ---------- epilogue: bias + relu; write fp32 h and (optionally) hi/lo ----------
    float2 bv[4];
    #pragma unroll
    for (int nt = 0; nt < 4; nt++) {
        int col = nBase + nt * 8 + (lane & 3) * 2;
        bv[nt].x = bias[col];
        bv[nt].y = bias[col + 1];
    }
    #pragma unroll
    for (int mt = 0; mt < 4; mt++) {
        #pragma unroll
        for (int half = 0; half < 2; half++) {
            int row = mb + mBase + mt * 16 + (lane >> 2) + half * 8;
            if (row >= N_NODES) continue;
            #pragma unroll
            for (int nt = 0; nt < 4; nt++) {
                int col = nBase + nt * 8 + (lane & 3) * 2;
                float v0 = fmaxf(acc[mt][nt][half * 2 + 0] + bv[nt].x, 0.f);
                float v1 = fmaxf(acc[mt][nt][half * 2 + 1] + bv[nt].y, 0.f);
                *(float2*)(out + (size_t)row * DF + col) = make_float2(v0, v1);
                if (oHi != nullptr) {
                    bf16 h0 = __float2bfloat16_rn(v0);
                    bf16 h1 = __float2bfloat16_rn(v1);
                    __nv_bfloat162 hp; hp.x = h0; hp.y = h1;
                    *(__nv_bfloat162*)(oHi + (size_t)row * DF + col) = hp;
                    __nv_bfloat162 lp;
                    lp.x = __float2bfloat16_rn(v0 - __bfloat162float(h0));
                    lp.y = __float2bfloat16_rn(v1 - __bfloat162float(h1));
                    *(__nv_bfloat162*)(oLo + (size_t)row * DF + col) = lp;
                }
            }
        }
    }
}

// ---------------- launch ----------------
extern "C" void kernel_launch(void* const* d_in, const int* in_sizes, int n_in,
                              void* d_out, int out_size) {
    const float* x  = (const float*)d_in[0];
    const int*   ei = (const int*)d_in[1];
    const float* W1 = (const float*)d_in[2];
    const float* b1 = (const float*)d_in[3];
    const float* R1 = (const float*)d_in[4];
    const float* W2 = (const float*)d_in[5];
    const float* b2 = (const float*)d_in[6];
    const float* R2 = (const float*)d_in[7];
    float* out = (float*)d_out;

    const int* src = ei;
    const int* dst = ei + N_EDGES;

    float *p_h0, *p_h1;
    bf16 *p_h0Hi, *p_h0Lo, *p_h1Hi, *p_h1Lo, *p_xHi, *p_xLo, *p_aggHi, *p_aggLo, *p_BT1, *p_BT2;
    cudaGetSymbolAddress((void**)&p_h0,    g_h0);
    cudaGetSymbolAddress((void**)&p_h1,    g_h1);
    cudaGetSymbolAddress((void**)&p_h0Hi,  g_h0Hi);
    cudaGetSymbolAddress((void**)&p_h0Lo,  g_h0Lo);
    cudaGetSymbolAddress((void**)&p_h1Hi,  g_h1Hi);
    cudaGetSymbolAddress((void**)&p_h1Lo,  g_h1Lo);
    cudaGetSymbolAddress((void**)&p_xHi,   g_xHi);
    cudaGetSymbolAddress((void**)&p_xLo,   g_xLo);
    cudaGetSymbolAddress((void**)&p_aggHi, g_aggHi);
    cudaGetSymbolAddress((void**)&p_aggLo, g_aggLo);
    cudaGetSymbolAddress((void**)&p_BT1,   g_BT1);
    cudaGetSymbolAddress((void**)&p_BT2,   g_BT2);

    static bool attrSet = false;
    if (!attrSet) {
        cudaFuncSetAttribute(gemm_kernel,
                             cudaFuncAttributeMaxDynamicSharedMemorySize, SMEM_BYTES);
        attrSet = true;
    }

    // preprocessing
    zero_counts_kernel<<<(N_NODES + 256) / 256, 256>>>();
    hist_kernel<<<(N_EDGES + 255) / 256, 256>>>(dst);
    scan1_kernel<<<NB_SCAN, 1024>>>();
    scan3_kernel<<<NB_SCAN, 1024>>>();
    scatter_kernel<<<(N_EDGES + 255) / 256, 256>>>(src, dst);
    prep_kernel<<<(N_NODES * DF + 255) / 256, 256>>>(W1, R1, W2, R2, x);

    const int aggBlocks  = (N_NODES * 32 + 255) / 256;
    const int gemmBlocks = (N_NODES + 127) / 128;

    // layer 1
    agg_kernel<<<aggBlocks, 256>>>(x);
    gemm_kernel<<<gemmBlocks, 256, SMEM_BYTES>>>(p_aggHi, p_aggLo, p_xHi, p_xLo, p_BT1, b1,
                                                 p_h0, p_h0Hi, p_h0Lo);
    // layer 2
    agg_kernel<<<aggBlocks, 256>>>(p_h0);
    gemm_kernel<<<gemmBlocks, 256, SMEM_BYTES>>>(p_aggHi, p_aggLo, p_h0Hi, p_h0Lo, p_BT2, b2,
                                                 p_h1, p_h1Hi, p_h1Lo);
    // layer 3
    agg_kernel<<<aggBlocks, 256>>>(p_h1);
    gemm_kernel<<<gemmBlocks, 256, SMEM_BYTES>>>(p_aggHi, p_aggLo, p_h1Hi, p_h1Lo, p_BT2, b2,
                                                 p_h0, p_h0Hi, p_h0Lo);
    // layer 4
    agg_kernel<<<aggBlocks, 256>>>(p_h0);
    gemm_kernel<<<gemmBlocks, 256, SMEM_BYTES>>>(p_aggHi, p_aggLo, p_h0Hi, p_h0Lo, p_BT2, b2,
                                                 out, nullptr, nullptr);
}